// round 2
// baseline (speedup 1.0000x reference)
#include <cuda_runtime.h>
#include <math.h>

#define NN 50000
#define EE 800000
#define NEG_SLOPE 0.2f

// ---------------- scratch (no allocations allowed) ----------------
__device__ float g_ft[NN * 194];     // projected features of current layer
__device__ float g_h[NN * 128];      // hidden state between layers
__device__ float g_rst[NN * 194];    // aggregation accumulator (bias+residual preloaded)
__device__ float g_res2[NN * 194];   // linear residual for layer 2
__device__ float g_el[NN * 2];
__device__ float g_er[NN * 2];
__device__ float g_emax[NN * 2];
__device__ float g_denom[NN * 2];
__device__ float g_e[EE * 2];        // edge logits, later overwritten with exp()

// ---------------- helpers ----------------
__device__ __forceinline__ void atomicMaxFloat(float* addr, float val) {
    int old = __float_as_int(*addr);
    while (__int_as_float(old) < val) {
        int assumed = old;
        old = atomicCAS((int*)addr, assumed, __float_as_int(val));
        if (old == assumed) break;
    }
}

// ---------------- GEMM: C[N,M] = A[N,128] @ B[128,M] ----------------
__global__ void gemm128(const float* __restrict__ A, const float* __restrict__ B,
                        float* __restrict__ C, int N, int M) {
    const int BM = 64, BN = 64, BK = 16, TM = 4, TN = 4;
    __shared__ float As[BK][BM + 1];
    __shared__ float Bs[BK][BN + 1];
    int tid = threadIdx.x;                 // 256 threads
    int block_row = blockIdx.y * BM;
    int block_col = blockIdx.x * BN;
    int tr = tid / (BN / TN);              // 0..15
    int tc = tid % (BN / TN);              // 0..15
    float acc[TM][TN] = {};
    for (int k0 = 0; k0 < 128; k0 += BK) {
        #pragma unroll
        for (int i = tid; i < BM * BK; i += 256) {
            int r = i / BK, c = i % BK;
            int gr = block_row + r;
            As[c][r] = (gr < N) ? A[gr * 128 + k0 + c] : 0.f;
        }
        #pragma unroll
        for (int i = tid; i < BK * BN; i += 256) {
            int r = i / BN, c = i % BN;
            int gc = block_col + c;
            Bs[r][c] = (gc < M) ? B[(k0 + r) * M + gc] : 0.f;
        }
        __syncthreads();
        #pragma unroll
        for (int k = 0; k < BK; k++) {
            float a[TM], b[TN];
            #pragma unroll
            for (int i = 0; i < TM; i++) a[i] = As[k][tr * TM + i];
            #pragma unroll
            for (int j = 0; j < TN; j++) b[j] = Bs[k][tc * TN + j];
            #pragma unroll
            for (int i = 0; i < TM; i++)
                #pragma unroll
                for (int j = 0; j < TN; j++) acc[i][j] += a[i] * b[j];
        }
        __syncthreads();
    }
    #pragma unroll
    for (int i = 0; i < TM; i++) {
        int gr = block_row + tr * TM + i;
        if (gr >= N) continue;
        #pragma unroll
        for (int j = 0; j < TN; j++) {
            int gc = block_col + tc * TN + j;
            if (gc < M) C[gr * M + gc] = acc[i][j];
        }
    }
}

// ---------------- el/er: per (node, head) dot with al/ar ----------------
__global__ void el_er_kernel(const float* __restrict__ ft,
                             const float* __restrict__ al, const float* __restrict__ ar,
                             float* __restrict__ el, float* __restrict__ er,
                             int N, int H, int D) {
    int idx = blockIdx.x * blockDim.x + threadIdx.x;
    if (idx >= N * H) return;
    int n = idx / H, h = idx % H;
    const float* f = ft + (n * H + h) * D;
    const float* pal = al + h * D;
    const float* par = ar + h * D;
    float sl = 0.f, sr = 0.f;
    for (int d = 0; d < D; d++) {
        float v = f[d];
        sl += v * pal[d];
        sr += v * par[d];
    }
    el[idx] = sl;
    er[idx] = sr;
}

// ---------------- init kernels ----------------
__global__ void init_attn(float* __restrict__ emax, float* __restrict__ denom, int n) {
    int i = blockIdx.x * blockDim.x + threadIdx.x;
    if (i >= n) return;
    emax[i] = __int_as_float(0xff800000);  // -inf
    denom[i] = 0.f;
}

// rst = bias(broadcast over nodes) + optional residual
__global__ void init_rst(float* __restrict__ rst, const float* __restrict__ bias,
                         const float* __restrict__ res, int N, int F) {
    int i = blockIdx.x * blockDim.x + threadIdx.x;
    if (i >= N * F) return;
    float v = bias[i % F];
    if (res) v += res[i];
    rst[i] = v;
}

// ---------------- edge pass A: logits + segment max ----------------
__global__ void edge_max(const int* __restrict__ src, const int* __restrict__ dst,
                         const float* __restrict__ el, const float* __restrict__ er,
                         float* __restrict__ e, float* __restrict__ emax, int E, int H) {
    int idx = blockIdx.x * blockDim.x + threadIdx.x;
    if (idx >= E * H) return;
    int ed = idx / H, h = idx % H;
    int s = src[ed], d = dst[ed];
    float v = el[s * H + h] + er[d * H + h];
    v = (v > 0.f) ? v : NEG_SLOPE * v;
    e[idx] = v;
    atomicMaxFloat(&emax[d * H + h], v);
}

// ---------------- edge pass B: exp + segment sum ----------------
__global__ void edge_exp(const int* __restrict__ dst,
                         float* __restrict__ e, const float* __restrict__ emax,
                         float* __restrict__ denom, int E, int H) {
    int idx = blockIdx.x * blockDim.x + threadIdx.x;
    if (idx >= E * H) return;
    int ed = idx / H, h = idx % H;
    int d = dst[ed];
    float ex = expf(e[idx] - emax[d * H + h]);
    e[idx] = ex;
    atomicAdd(&denom[d * H + h], ex);
}

// ---------------- edge pass C: weighted scatter ----------------
__global__ void edge_scatter(const int* __restrict__ src, const int* __restrict__ dst,
                             const float* __restrict__ ft, const float* __restrict__ ex,
                             const float* __restrict__ denom, float* __restrict__ rst,
                             int E, int H, int D) {
    int F = H * D;
    int idx = blockIdx.x * blockDim.x + threadIdx.x;
    if (idx >= E * F) return;
    int ed = idx / F;
    int hd = idx - ed * F;
    int h = hd / D;
    int s = src[ed], d = dst[ed];
    float a = ex[ed * H + h] / denom[d * H + h];
    atomicAdd(&rst[d * F + hd], ft[s * F + hd] * a);
}

// ---------------- epilogues ----------------
__global__ void elu_kernel(const float* __restrict__ rst, float* __restrict__ out, int n) {
    int i = blockIdx.x * blockDim.x + threadIdx.x;
    if (i >= n) return;
    float v = rst[i];
    out[i] = (v > 0.f) ? v : (expf(v) - 1.f);
}

// mean over 2 heads, drop last node
__global__ void final_kernel(const float* __restrict__ rst, float* __restrict__ out,
                             int Nout, int D) {
    int idx = blockIdx.x * blockDim.x + threadIdx.x;
    if (idx >= Nout * D) return;
    int n = idx / D, c = idx - n * D;
    out[idx] = 0.5f * (rst[n * 2 * D + c] + rst[n * 2 * D + D + c]);
}

// ---------------- host-side orchestration ----------------
static inline int divup(int a, int b) { return (a + b - 1) / b; }

struct Scratch {
    float *ft, *h, *rst, *res2, *el, *er, *emax, *denom, *e;
};

static void get_scratch(Scratch& s) {
    cudaGetSymbolAddress((void**)&s.ft, g_ft);
    cudaGetSymbolAddress((void**)&s.h, g_h);
    cudaGetSymbolAddress((void**)&s.rst, g_rst);
    cudaGetSymbolAddress((void**)&s.res2, g_res2);
    cudaGetSymbolAddress((void**)&s.el, g_el);
    cudaGetSymbolAddress((void**)&s.er, g_er);
    cudaGetSymbolAddress((void**)&s.emax, g_emax);
    cudaGetSymbolAddress((void**)&s.denom, g_denom);
    cudaGetSymbolAddress((void**)&s.e, g_e);
}

static void run_gat_layer(const Scratch& s,
                          const float* h_in,      // [N,128]
                          const int* src, const int* dst,
                          const float* W,         // [128, H*D]
                          const float* al, const float* ar,   // [H,D]
                          const float* bias,      // [H*D]
                          const float* res,       // [N,H*D] or nullptr
                          int H, int D,
                          float* out,             // [N,H*D] (elu) — or nullptr if no epilogue
                          bool do_elu) {
    const int N = NN, E = EE;
    const int F = H * D;

    // 1. ft = h_in @ W
    dim3 ggrid(divup(F, 64), divup(N, 64));
    gemm128<<<ggrid, 256>>>(h_in, W, s.ft, N, F);

    // 2. el/er
    el_er_kernel<<<divup(N * H, 256), 256>>>(s.ft, al, ar, s.el, s.er, N, H, D);

    // 3. init attention state + rst (= bias + residual)
    init_attn<<<divup(N * H, 256), 256>>>(s.emax, s.denom, N * H);
    init_rst<<<divup(N * F, 256), 256>>>(s.rst, bias, res, N, F);

    // 4. edge softmax passes
    edge_max<<<divup(E * H, 256), 256>>>(src, dst, s.el, s.er, s.e, s.emax, E, H);
    edge_exp<<<divup(E * H, 256), 256>>>(dst, s.e, s.emax, s.denom, E, H);
    edge_scatter<<<divup(E * F, 256), 256>>>(src, dst, s.ft, s.e, s.denom, s.rst, E, H, D);

    // 5. activation epilogue
    if (do_elu)
        elu_kernel<<<divup(N * F, 256), 256>>>(s.rst, out, N * F);
}

extern "C" void kernel_launch(void* const* d_in, const int* in_sizes, int n_in,
                              void* d_out, int out_size) {
    const float* x        = (const float*)d_in[0];
    const int*   src      = (const int*)d_in[1];
    const int*   dst      = (const int*)d_in[2];
    const float* W0       = (const float*)d_in[3];
    const float* al0      = (const float*)d_in[4];
    const float* ar0      = (const float*)d_in[5];
    const float* b0       = (const float*)d_in[6];
    const float* W1       = (const float*)d_in[7];
    const float* al1      = (const float*)d_in[8];
    const float* ar1      = (const float*)d_in[9];
    const float* b1       = (const float*)d_in[10];
    const float* W2       = (const float*)d_in[11];
    const float* al2      = (const float*)d_in[12];
    const float* ar2      = (const float*)d_in[13];
    const float* b2       = (const float*)d_in[14];
    const float* res_W2   = (const float*)d_in[15];
    float* out = (float*)d_out;

    Scratch s;
    get_scratch(s);

    const int N = NN;

    // ---- layer 0: no residual, ELU, H=2 D=64 ----
    run_gat_layer(s, x, src, dst, W0, al0, ar0, b0, /*res=*/nullptr, 2, 64, s.h, true);

    // ---- layer 1: identity residual (= current h), ELU ----
    run_gat_layer(s, s.h, src, dst, W1, al1, ar1, b1, /*res=*/s.h, 2, 64, s.h, true);

    // ---- layer 2: linear residual h@res_W2, no activation, H=2 D=97 ----
    {
        dim3 ggrid(divup(194, 64), divup(N, 64));
        gemm128<<<ggrid, 256>>>(s.h, res_W2, s.res2, N, 194);
    }
    run_gat_layer(s, s.h, src, dst, W2, al2, ar2, b2, /*res=*/s.res2, 2, 97,
                  /*out=*/nullptr, /*do_elu=*/false);

    // ---- mean over heads + drop last node ----
    final_kernel<<<divup((N - 1) * 97, 256), 256>>>(s.rst, out, N - 1, 97);
}

// round 3
// speedup vs baseline: 2.2817x; 2.2817x over previous
#include <cuda_runtime.h>
#include <math.h>

#define NN 50000
#define EE 800000
#define NEG_SLOPE 0.2f

// ---------------- scratch (no allocations allowed) ----------------
__device__ float g_ft[NN * 194];     // projected features of current layer
__device__ float g_h[NN * 128];      // hidden state between layers
__device__ float g_rst[NN * 194];    // layer-2 aggregation output
__device__ float g_res2[NN * 194];   // linear residual for layer 2
__device__ float g_el[NN * 2];
__device__ float g_er[NN * 2];
__device__ float g_w[EE * 2];        // per (sorted-edge, head) attention weights
__device__ int   g_deg[NN];
__device__ int   g_rowptr[NN + 1];
__device__ int   g_cursor[NN];
__device__ int   g_esrc[EE];         // src node of edges, bucketed by dst

// ---------------- GEMM: C[N,M] = A[N,128] @ B[128,M] ----------------
__global__ void gemm128(const float* __restrict__ A, const float* __restrict__ B,
                        float* __restrict__ C, int N, int M) {
    const int BM = 64, BN = 64, BK = 16, TM = 4, TN = 4;
    __shared__ float As[BK][BM + 1];
    __shared__ float Bs[BK][BN + 1];
    int tid = threadIdx.x;                 // 256 threads
    int block_row = blockIdx.y * BM;
    int block_col = blockIdx.x * BN;
    int tr = tid / (BN / TN);              // 0..15
    int tc = tid % (BN / TN);              // 0..15
    float acc[TM][TN] = {};
    for (int k0 = 0; k0 < 128; k0 += BK) {
        #pragma unroll
        for (int i = tid; i < BM * BK; i += 256) {
            int r = i / BK, c = i % BK;
            int gr = block_row + r;
            As[c][r] = (gr < N) ? A[gr * 128 + k0 + c] : 0.f;
        }
        #pragma unroll
        for (int i = tid; i < BK * BN; i += 256) {
            int r = i / BN, c = i % BN;
            int gc = block_col + c;
            Bs[r][c] = (gc < M) ? B[(k0 + r) * M + gc] : 0.f;
        }
        __syncthreads();
        #pragma unroll
        for (int k = 0; k < BK; k++) {
            float a[TM], b[TN];
            #pragma unroll
            for (int i = 0; i < TM; i++) a[i] = As[k][tr * TM + i];
            #pragma unroll
            for (int j = 0; j < TN; j++) b[j] = Bs[k][tc * TN + j];
            #pragma unroll
            for (int i = 0; i < TM; i++)
                #pragma unroll
                for (int j = 0; j < TN; j++) acc[i][j] += a[i] * b[j];
        }
        __syncthreads();
    }
    #pragma unroll
    for (int i = 0; i < TM; i++) {
        int gr = block_row + tr * TM + i;
        if (gr >= N) continue;
        #pragma unroll
        for (int j = 0; j < TN; j++) {
            int gc = block_col + tc * TN + j;
            if (gc < M) C[gr * M + gc] = acc[i][j];
        }
    }
}

// ---------------- CSR build ----------------
__global__ void zero_deg(int* __restrict__ deg, int n) {
    int i = blockIdx.x * blockDim.x + threadIdx.x;
    if (i < n) deg[i] = 0;
}

__global__ void hist_dst(const int* __restrict__ dst, int* __restrict__ deg, int E) {
    int e = blockIdx.x * blockDim.x + threadIdx.x;
    if (e < E) atomicAdd(&deg[dst[e]], 1);
}

// single-block exclusive scan over NN elements (1024 threads)
__global__ void exscan_kernel(const int* __restrict__ deg, int* __restrict__ rowptr,
                              int* __restrict__ cursor, int n) {
    __shared__ int sh[1024];
    int t = threadIdx.x;
    const int CH = (n + 1023) / 1024;
    int base = t * CH;
    int sum = 0;
    for (int i = 0; i < CH; i++) {
        int idx = base + i;
        if (idx < n) sum += deg[idx];
    }
    sh[t] = sum;
    __syncthreads();
    for (int off = 1; off < 1024; off <<= 1) {
        int v = (t >= off) ? sh[t - off] : 0;
        __syncthreads();
        sh[t] += v;
        __syncthreads();
    }
    int run = (t == 0) ? 0 : sh[t - 1];
    for (int i = 0; i < CH; i++) {
        int idx = base + i;
        if (idx < n) {
            rowptr[idx] = run;
            cursor[idx] = run;
            run += deg[idx];
        }
    }
    if (t == 1023) rowptr[n] = sh[1023];
}

__global__ void fill_csr(const int* __restrict__ src, const int* __restrict__ dst,
                         int* __restrict__ cursor, int* __restrict__ esrc, int E) {
    int e = blockIdx.x * blockDim.x + threadIdx.x;
    if (e >= E) return;
    int pos = atomicAdd(&cursor[dst[e]], 1);
    esrc[pos] = src[e];
}

// ---------------- el/er ----------------
__global__ void el_er_kernel(const float* __restrict__ ft,
                             const float* __restrict__ al, const float* __restrict__ ar,
                             float* __restrict__ el, float* __restrict__ er,
                             int N, int H, int D) {
    int idx = blockIdx.x * blockDim.x + threadIdx.x;
    if (idx >= N * H) return;
    int n = idx / H, h = idx % H;
    const float* f = ft + (n * H + h) * D;
    const float* pal = al + h * D;
    const float* par = ar + h * D;
    float sl = 0.f, sr = 0.f;
    for (int d = 0; d < D; d++) {
        float v = f[d];
        sl += v * pal[d];
        sr += v * par[d];
    }
    el[idx] = sl;
    er[idx] = sr;
}

// ---------------- warp-per-node edge softmax (writes weights) ----------------
__global__ void node_softmax(const int* __restrict__ rowptr, const int* __restrict__ esrc,
                             const float* __restrict__ el, const float* __restrict__ er,
                             float* __restrict__ w, int N) {
    int warp = (blockIdx.x * blockDim.x + threadIdx.x) >> 5;
    int lane = threadIdx.x & 31;
    if (warp >= N) return;
    int start = rowptr[warp], end = rowptr[warp + 1];
    if (start == end) return;
    float er0 = er[warp * 2], er1 = er[warp * 2 + 1];

    // pass 1: max
    float m0 = -INFINITY, m1 = -INFINITY;
    for (int i = start + lane; i < end; i += 32) {
        int s = esrc[i];
        float v0 = el[s * 2] + er0;     v0 = (v0 > 0.f) ? v0 : NEG_SLOPE * v0;
        float v1 = el[s * 2 + 1] + er1; v1 = (v1 > 0.f) ? v1 : NEG_SLOPE * v1;
        m0 = fmaxf(m0, v0); m1 = fmaxf(m1, v1);
    }
    #pragma unroll
    for (int o = 16; o > 0; o >>= 1) {
        m0 = fmaxf(m0, __shfl_xor_sync(0xffffffff, m0, o));
        m1 = fmaxf(m1, __shfl_xor_sync(0xffffffff, m1, o));
    }

    // pass 2: exp + sum (store exp)
    float s0 = 0.f, s1 = 0.f;
    for (int i = start + lane; i < end; i += 32) {
        int s = esrc[i];
        float v0 = el[s * 2] + er0;     v0 = (v0 > 0.f) ? v0 : NEG_SLOPE * v0;
        float v1 = el[s * 2 + 1] + er1; v1 = (v1 > 0.f) ? v1 : NEG_SLOPE * v1;
        float e0 = __expf(v0 - m0), e1 = __expf(v1 - m1);
        w[i * 2] = e0; w[i * 2 + 1] = e1;
        s0 += e0; s1 += e1;
    }
    #pragma unroll
    for (int o = 16; o > 0; o >>= 1) {
        s0 += __shfl_xor_sync(0xffffffff, s0, o);
        s1 += __shfl_xor_sync(0xffffffff, s1, o);
    }
    float inv0 = 1.f / s0, inv1 = 1.f / s1;

    // pass 3: normalize
    for (int i = start + lane; i < end; i += 32) {
        w[i * 2]     *= inv0;
        w[i * 2 + 1] *= inv1;
    }
}

// ---------------- block-per-node aggregation, fused bias+residual+ELU ----------------
// blockDim.x >= F; thread = feature channel hd; h = hd / D.
__global__ void node_aggregate(const int* __restrict__ rowptr, const int* __restrict__ esrc,
                               const float* __restrict__ ft, const float* __restrict__ w,
                               const float* __restrict__ bias, const float* __restrict__ res,
                               float* __restrict__ out, int F, int D, int do_elu) {
    int n = blockIdx.x;
    int hd = threadIdx.x;
    if (hd >= F) return;
    int h = (hd >= D) ? 1 : 0;
    float acc = bias[hd];
    if (res) acc += res[n * F + hd];

    int start = rowptr[n], end = rowptr[n + 1];
    int i = start;
    for (; i + 3 < end; i += 4) {
        int s0 = esrc[i], s1 = esrc[i + 1], s2 = esrc[i + 2], s3 = esrc[i + 3];
        float w0 = w[i * 2 + h], w1 = w[(i + 1) * 2 + h];
        float w2 = w[(i + 2) * 2 + h], w3 = w[(i + 3) * 2 + h];
        float f0 = ft[s0 * F + hd], f1 = ft[s1 * F + hd];
        float f2 = ft[s2 * F + hd], f3 = ft[s3 * F + hd];
        acc += f0 * w0 + f1 * w1 + f2 * w2 + f3 * w3;
    }
    for (; i < end; i++) {
        int s = esrc[i];
        acc += ft[s * F + hd] * w[i * 2 + h];
    }

    if (do_elu) acc = (acc > 0.f) ? acc : (__expf(acc) - 1.f);
    out[n * F + hd] = acc;
}

// ---------------- final: mean over 2 heads, drop last node ----------------
__global__ void final_kernel(const float* __restrict__ rst, float* __restrict__ out,
                             int Nout, int D) {
    int idx = blockIdx.x * blockDim.x + threadIdx.x;
    if (idx >= Nout * D) return;
    int n = idx / D, c = idx - n * D;
    out[idx] = 0.5f * (rst[n * 2 * D + c] + rst[n * 2 * D + D + c]);
}

// ---------------- host-side orchestration ----------------
static inline int divup(int a, int b) { return (a + b - 1) / b; }

struct Scratch {
    float *ft, *h, *rst, *res2, *el, *er, *w;
    int *deg, *rowptr, *cursor, *esrc;
};

static void get_scratch(Scratch& s) {
    cudaGetSymbolAddress((void**)&s.ft, g_ft);
    cudaGetSymbolAddress((void**)&s.h, g_h);
    cudaGetSymbolAddress((void**)&s.rst, g_rst);
    cudaGetSymbolAddress((void**)&s.res2, g_res2);
    cudaGetSymbolAddress((void**)&s.el, g_el);
    cudaGetSymbolAddress((void**)&s.er, g_er);
    cudaGetSymbolAddress((void**)&s.w, g_w);
    cudaGetSymbolAddress((void**)&s.deg, g_deg);
    cudaGetSymbolAddress((void**)&s.rowptr, g_rowptr);
    cudaGetSymbolAddress((void**)&s.cursor, g_cursor);
    cudaGetSymbolAddress((void**)&s.esrc, g_esrc);
}

static void run_gat_layer(const Scratch& s,
                          const float* h_in,      // [N,128]
                          const float* W,         // [128, H*D]
                          const float* al, const float* ar,
                          const float* bias,
                          const float* res,       // [N,H*D] or nullptr
                          int D,                  // per-head dim (H = 2)
                          float* out, bool do_elu) {
    const int N = NN;
    const int F = 2 * D;

    // 1. ft = h_in @ W
    dim3 ggrid(divup(F, 64), divup(N, 64));
    gemm128<<<ggrid, 256>>>(h_in, W, s.ft, N, F);

    // 2. el/er
    el_er_kernel<<<divup(N * 2, 256), 256>>>(s.ft, al, ar, s.el, s.er, N, 2, D);

    // 3. per-node softmax over incoming edges -> weights
    node_softmax<<<divup(N * 32, 256), 256>>>(s.rowptr, s.esrc, s.el, s.er, s.w, N);

    // 4. gather-aggregate with fused bias/residual/ELU
    int bdim = divup(F, 32) * 32;   // 128 or 224
    node_aggregate<<<N, bdim>>>(s.rowptr, s.esrc, s.ft, s.w, bias, res, out, F, D, do_elu ? 1 : 0);
}

extern "C" void kernel_launch(void* const* d_in, const int* in_sizes, int n_in,
                              void* d_out, int out_size) {
    const float* x      = (const float*)d_in[0];
    const int*   src    = (const int*)d_in[1];
    const int*   dst    = (const int*)d_in[2];
    const float* W0     = (const float*)d_in[3];
    const float* al0    = (const float*)d_in[4];
    const float* ar0    = (const float*)d_in[5];
    const float* b0     = (const float*)d_in[6];
    const float* W1     = (const float*)d_in[7];
    const float* al1    = (const float*)d_in[8];
    const float* ar1    = (const float*)d_in[9];
    const float* b1     = (const float*)d_in[10];
    const float* W2     = (const float*)d_in[11];
    const float* al2    = (const float*)d_in[12];
    const float* ar2    = (const float*)d_in[13];
    const float* b2     = (const float*)d_in[14];
    const float* res_W2 = (const float*)d_in[15];
    float* out = (float*)d_out;

    Scratch s;
    get_scratch(s);

    const int N = NN, E = EE;

    // ---- CSR build (once; shared by all 3 layers) ----
    zero_deg<<<divup(N, 256), 256>>>(s.deg, N);
    hist_dst<<<divup(E, 256), 256>>>(dst, s.deg, E);
    exscan_kernel<<<1, 1024>>>(s.deg, s.rowptr, s.cursor, N);
    fill_csr<<<divup(E, 256), 256>>>(src, dst, s.cursor, s.esrc, E);

    // ---- layer 0: no residual, ELU, D=64 ----
    run_gat_layer(s, x, W0, al0, ar0, b0, nullptr, 64, s.h, true);

    // ---- layer 1: identity residual, ELU, D=64 ----
    run_gat_layer(s, s.h, W1, al1, ar1, b1, s.h, 64, s.h, true);

    // ---- layer 2: linear residual h@res_W2, no activation, D=97 ----
    {
        dim3 ggrid(divup(194, 64), divup(N, 64));
        gemm128<<<ggrid, 256>>>(s.h, res_W2, s.res2, N, 194);
    }
    run_gat_layer(s, s.h, W2, al2, ar2, b2, s.res2, 97, s.rst, false);

    // ---- mean over heads + drop last node ----
    final_kernel<<<divup((N - 1) * 97, 256), 256>>>(s.rst, out, N - 1, 97);
}

// round 4
// speedup vs baseline: 3.0498x; 1.3366x over previous
#include <cuda_runtime.h>
#include <math.h>

#define NN 50000
#define EE 800000
#define NEG_SLOPE 0.2f

// ---------------- scratch (no allocations allowed) ----------------
__device__ float g_ft[NN * 194];
__device__ float g_h[NN * 128];
__device__ float g_rst[NN * 194];
__device__ float g_res2[NN * 194];
__device__ float g_el[NN * 2];
__device__ float g_er[NN * 2];
__device__ float g_w[EE * 2];
__device__ int   g_deg[NN];
__device__ int   g_rowptr[NN + 1];
__device__ int   g_cursor[NN];
__device__ int   g_esrc[EE];

// ================= TF32 tensor-core GEMM =================
// C[Nrows, Mcols] = A[Nrows,128] @ B[128,Mcols], fp32 in/out,
// 3xTF32 split for fp32-level accuracy.
// Block tile 128x64, BK=32, full-K B slice resident in smem.

__device__ __forceinline__ unsigned f2tf32(float x) {
    unsigned r;
    asm("cvt.rna.tf32.f32 %0, %1;" : "=r"(r) : "f"(x));
    return r;
}

__device__ __forceinline__ void mma_tf32(float* c, const unsigned* a, const unsigned* b) {
    asm volatile(
        "mma.sync.aligned.m16n8k8.row.col.f32.tf32.tf32.f32 "
        "{%0,%1,%2,%3}, {%4,%5,%6,%7}, {%8,%9}, {%0,%1,%2,%3};\n"
        : "+f"(c[0]), "+f"(c[1]), "+f"(c[2]), "+f"(c[3])
        : "r"(a[0]), "r"(a[1]), "r"(a[2]), "r"(a[3]), "r"(b[0]), "r"(b[1]));
}

#define GBM 128
#define GBN 64
#define GBK 32
#define ASTR 36   // A smem row stride (words): [128][36]
#define BSTR 72   // B smem row stride (words): [128][72]
// smem floats: A_hi 128*36, A_lo 128*36, B_hi 128*72, B_lo 128*72
#define GEMM_SMEM_FLOATS (2 * 128 * ASTR + 2 * 128 * BSTR)

__global__ void __launch_bounds__(256, 2)
gemm_tf32(const float* __restrict__ A, const float* __restrict__ B,
          float* __restrict__ C, int Nrows, int Mcols) {
    extern __shared__ float sm[];
    float* Ah = sm;                        // [128][ASTR]
    float* Al = Ah + 128 * ASTR;
    float* Bh = Al + 128 * ASTR;           // [128][BSTR]
    float* Bl = Bh + 128 * BSTR;

    const int tid = threadIdx.x;
    const int lane = tid & 31;
    const int warp = tid >> 5;
    const int wm = warp & 3;               // 0..3 along M
    const int wn = warp >> 2;              // 0..1 along N
    const int row0 = blockIdx.y * GBM;
    const int col0 = blockIdx.x * GBN;

    // ---- load full B slice [128 x 64] hi/lo (once) ----
    #pragma unroll 8
    for (int i = 0; i < 32; i++) {
        int e = tid + i * 256;             // 0..8191
        int c = e & 63;
        int k = e >> 6;
        float v = 0.f;
        int gc = col0 + c;
        if (gc < Mcols) v = B[k * Mcols + gc];
        float hi = __uint_as_float(f2tf32(v));
        float lo = __uint_as_float(f2tf32(v - hi));
        Bh[k * BSTR + c] = hi;
        Bl[k * BSTR + c] = lo;
    }

    float acc[2][4][4];
    #pragma unroll
    for (int mt = 0; mt < 2; mt++)
        #pragma unroll
        for (int nt = 0; nt < 4; nt++)
            #pragma unroll
            for (int j = 0; j < 4; j++) acc[mt][nt][j] = 0.f;

    const int qr = lane >> 2;   // 0..7
    const int qc = lane & 3;    // 0..3

    for (int kt = 0; kt < 4; kt++) {
        // ---- load A chunk [128 rows x 32 cols] hi/lo, coalesced float4 ----
        __syncthreads();
        #pragma unroll
        for (int i = 0; i < 4; i++) {
            int e = tid + i * 256;         // 0..1023 float4 units
            int r = e >> 3;                // 0..127
            int seg = e & 7;               // 0..7 (4 floats each)
            int gr = row0 + r;
            float4 v;
            if (gr < Nrows) v = *(const float4*)(A + gr * 128 + kt * 32 + seg * 4);
            else            v = make_float4(0.f, 0.f, 0.f, 0.f);
            float4 hi, lo;
            hi.x = __uint_as_float(f2tf32(v.x)); lo.x = __uint_as_float(f2tf32(v.x - hi.x));
            hi.y = __uint_as_float(f2tf32(v.y)); lo.y = __uint_as_float(f2tf32(v.y - hi.y));
            hi.z = __uint_as_float(f2tf32(v.z)); lo.z = __uint_as_float(f2tf32(v.z - hi.z));
            hi.w = __uint_as_float(f2tf32(v.w)); lo.w = __uint_as_float(f2tf32(v.w - hi.w));
            *(float4*)(Ah + r * ASTR + seg * 4) = hi;
            *(float4*)(Al + r * ASTR + seg * 4) = lo;
        }
        __syncthreads();

        #pragma unroll
        for (int ks = 0; ks < 4; ks++) {
            const int kk = ks * 8;              // within A chunk
            const int kg = kt * 32 + kk;        // global k for B

            unsigned aH[2][4], aL[2][4];
            #pragma unroll
            for (int mt = 0; mt < 2; mt++) {
                int r = wm * 32 + mt * 16 + qr;
                int base0 = r * ASTR + kk + qc;
                int base1 = (r + 8) * ASTR + kk + qc;
                aH[mt][0] = __float_as_uint(Ah[base0]);
                aH[mt][1] = __float_as_uint(Ah[base1]);
                aH[mt][2] = __float_as_uint(Ah[base0 + 4]);
                aH[mt][3] = __float_as_uint(Ah[base1 + 4]);
                aL[mt][0] = __float_as_uint(Al[base0]);
                aL[mt][1] = __float_as_uint(Al[base1]);
                aL[mt][2] = __float_as_uint(Al[base0 + 4]);
                aL[mt][3] = __float_as_uint(Al[base1 + 4]);
            }
            unsigned bH[4][2], bL[4][2];
            #pragma unroll
            for (int nt = 0; nt < 4; nt++) {
                int c = wn * 32 + nt * 8 + qr;
                int base0 = (kg + qc) * BSTR + c;
                int base1 = (kg + 4 + qc) * BSTR + c;
                bH[nt][0] = __float_as_uint(Bh[base0]);
                bH[nt][1] = __float_as_uint(Bh[base1]);
                bL[nt][0] = __float_as_uint(Bl[base0]);
                bL[nt][1] = __float_as_uint(Bl[base1]);
            }
            #pragma unroll
            for (int mt = 0; mt < 2; mt++)
                #pragma unroll
                for (int nt = 0; nt < 4; nt++) {
                    mma_tf32(acc[mt][nt], aH[mt], bH[nt]);
                    mma_tf32(acc[mt][nt], aH[mt], bL[nt]);
                    mma_tf32(acc[mt][nt], aL[mt], bH[nt]);
                }
        }
    }

    // ---- epilogue ----
    #pragma unroll
    for (int mt = 0; mt < 2; mt++) {
        int r = row0 + wm * 32 + mt * 16 + qr;
        #pragma unroll
        for (int nt = 0; nt < 4; nt++) {
            int c = col0 + wn * 32 + nt * 8 + qc * 2;
            if (r < Nrows) {
                if (c < Mcols)     C[r * Mcols + c]     = acc[mt][nt][0];
                if (c + 1 < Mcols) C[r * Mcols + c + 1] = acc[mt][nt][1];
            }
            if (r + 8 < Nrows) {
                if (c < Mcols)     C[(r + 8) * Mcols + c]     = acc[mt][nt][2];
                if (c + 1 < Mcols) C[(r + 8) * Mcols + c + 1] = acc[mt][nt][3];
            }
        }
    }
}

// ---------------- CSR build ----------------
__global__ void zero_deg(int* __restrict__ deg, int n) {
    int i = blockIdx.x * blockDim.x + threadIdx.x;
    if (i < n) deg[i] = 0;
}

__global__ void hist_dst(const int* __restrict__ dst, int* __restrict__ deg, int E) {
    int e = blockIdx.x * blockDim.x + threadIdx.x;
    if (e < E) atomicAdd(&deg[dst[e]], 1);
}

__global__ void exscan_kernel(const int* __restrict__ deg, int* __restrict__ rowptr,
                              int* __restrict__ cursor, int n) {
    __shared__ int sh[1024];
    int t = threadIdx.x;
    const int CH = (n + 1023) / 1024;
    int base = t * CH;
    int sum = 0;
    for (int i = 0; i < CH; i++) {
        int idx = base + i;
        if (idx < n) sum += deg[idx];
    }
    sh[t] = sum;
    __syncthreads();
    for (int off = 1; off < 1024; off <<= 1) {
        int v = (t >= off) ? sh[t - off] : 0;
        __syncthreads();
        sh[t] += v;
        __syncthreads();
    }
    int run = (t == 0) ? 0 : sh[t - 1];
    for (int i = 0; i < CH; i++) {
        int idx = base + i;
        if (idx < n) {
            rowptr[idx] = run;
            cursor[idx] = run;
            run += deg[idx];
        }
    }
    if (t == 1023) rowptr[n] = sh[1023];
}

__global__ void fill_csr(const int* __restrict__ src, const int* __restrict__ dst,
                         int* __restrict__ cursor, int* __restrict__ esrc, int E) {
    int e = blockIdx.x * blockDim.x + threadIdx.x;
    if (e >= E) return;
    int pos = atomicAdd(&cursor[dst[e]], 1);
    esrc[pos] = src[e];
}

// ---------------- el/er ----------------
__global__ void el_er_kernel(const float* __restrict__ ft,
                             const float* __restrict__ al, const float* __restrict__ ar,
                             float* __restrict__ el, float* __restrict__ er,
                             int N, int H, int D) {
    int idx = blockIdx.x * blockDim.x + threadIdx.x;
    if (idx >= N * H) return;
    int n = idx / H, h = idx % H;
    const float* f = ft + (n * H + h) * D;
    const float* pal = al + h * D;
    const float* par = ar + h * D;
    float sl = 0.f, sr = 0.f;
    for (int d = 0; d < D; d++) {
        float v = f[d];
        sl += v * pal[d];
        sr += v * par[d];
    }
    el[idx] = sl;
    er[idx] = sr;
}

// ---------------- warp-per-node edge softmax ----------------
__global__ void node_softmax(const int* __restrict__ rowptr, const int* __restrict__ esrc,
                             const float* __restrict__ el, const float* __restrict__ er,
                             float* __restrict__ w, int N) {
    int warp = (blockIdx.x * blockDim.x + threadIdx.x) >> 5;
    int lane = threadIdx.x & 31;
    if (warp >= N) return;
    int start = rowptr[warp], end = rowptr[warp + 1];
    if (start == end) return;
    float er0 = er[warp * 2], er1 = er[warp * 2 + 1];

    float m0 = -INFINITY, m1 = -INFINITY;
    for (int i = start + lane; i < end; i += 32) {
        int s = esrc[i];
        float v0 = el[s * 2] + er0;     v0 = (v0 > 0.f) ? v0 : NEG_SLOPE * v0;
        float v1 = el[s * 2 + 1] + er1; v1 = (v1 > 0.f) ? v1 : NEG_SLOPE * v1;
        m0 = fmaxf(m0, v0); m1 = fmaxf(m1, v1);
    }
    #pragma unroll
    for (int o = 16; o > 0; o >>= 1) {
        m0 = fmaxf(m0, __shfl_xor_sync(0xffffffff, m0, o));
        m1 = fmaxf(m1, __shfl_xor_sync(0xffffffff, m1, o));
    }

    float s0 = 0.f, s1 = 0.f;
    for (int i = start + lane; i < end; i += 32) {
        int s = esrc[i];
        float v0 = el[s * 2] + er0;     v0 = (v0 > 0.f) ? v0 : NEG_SLOPE * v0;
        float v1 = el[s * 2 + 1] + er1; v1 = (v1 > 0.f) ? v1 : NEG_SLOPE * v1;
        float e0 = __expf(v0 - m0), e1 = __expf(v1 - m1);
        w[i * 2] = e0; w[i * 2 + 1] = e1;
        s0 += e0; s1 += e1;
    }
    #pragma unroll
    for (int o = 16; o > 0; o >>= 1) {
        s0 += __shfl_xor_sync(0xffffffff, s0, o);
        s1 += __shfl_xor_sync(0xffffffff, s1, o);
    }
    float inv0 = 1.f / s0, inv1 = 1.f / s1;

    for (int i = start + lane; i < end; i += 32) {
        w[i * 2]     *= inv0;
        w[i * 2 + 1] *= inv1;
    }
}

// ---------------- block-per-node aggregation (fused bias+res+ELU) ----------------
__global__ void node_aggregate(const int* __restrict__ rowptr, const int* __restrict__ esrc,
                               const float* __restrict__ ft, const float* __restrict__ w,
                               const float* __restrict__ bias, const float* __restrict__ res,
                               float* __restrict__ out, int F, int D, int do_elu) {
    int n = blockIdx.x;
    int hd = threadIdx.x;
    if (hd >= F) return;
    int h = (hd >= D) ? 1 : 0;
    float acc = bias[hd];
    if (res) acc += res[n * F + hd];

    int start = rowptr[n], end = rowptr[n + 1];
    int i = start;
    for (; i + 3 < end; i += 4) {
        int s0 = esrc[i], s1 = esrc[i + 1], s2 = esrc[i + 2], s3 = esrc[i + 3];
        float w0 = w[i * 2 + h], w1 = w[(i + 1) * 2 + h];
        float w2 = w[(i + 2) * 2 + h], w3 = w[(i + 3) * 2 + h];
        float f0 = ft[s0 * F + hd], f1 = ft[s1 * F + hd];
        float f2 = ft[s2 * F + hd], f3 = ft[s3 * F + hd];
        acc += f0 * w0 + f1 * w1 + f2 * w2 + f3 * w3;
    }
    for (; i < end; i++) {
        int s = esrc[i];
        acc += ft[s * F + hd] * w[i * 2 + h];
    }

    if (do_elu) acc = (acc > 0.f) ? acc : (__expf(acc) - 1.f);
    out[n * F + hd] = acc;
}

// ---------------- final: mean over 2 heads, drop last node ----------------
__global__ void final_kernel(const float* __restrict__ rst, float* __restrict__ out,
                             int Nout, int D) {
    int idx = blockIdx.x * blockDim.x + threadIdx.x;
    if (idx >= Nout * D) return;
    int n = idx / D, c = idx - n * D;
    out[idx] = 0.5f * (rst[n * 2 * D + c] + rst[n * 2 * D + D + c]);
}

// ---------------- host-side orchestration ----------------
static inline int divup(int a, int b) { return (a + b - 1) / b; }

struct Scratch {
    float *ft, *h, *rst, *res2, *el, *er, *w;
    int *deg, *rowptr, *cursor, *esrc;
};

static void get_scratch(Scratch& s) {
    cudaGetSymbolAddress((void**)&s.ft, g_ft);
    cudaGetSymbolAddress((void**)&s.h, g_h);
    cudaGetSymbolAddress((void**)&s.rst, g_rst);
    cudaGetSymbolAddress((void**)&s.res2, g_res2);
    cudaGetSymbolAddress((void**)&s.el, g_el);
    cudaGetSymbolAddress((void**)&s.er, g_er);
    cudaGetSymbolAddress((void**)&s.w, g_w);
    cudaGetSymbolAddress((void**)&s.deg, g_deg);
    cudaGetSymbolAddress((void**)&s.rowptr, g_rowptr);
    cudaGetSymbolAddress((void**)&s.cursor, g_cursor);
    cudaGetSymbolAddress((void**)&s.esrc, g_esrc);
}

static void launch_gemm(const float* A, const float* B, float* C, int Nrows, int Mcols) {
    static bool attr_set = false;
    const int smem_bytes = GEMM_SMEM_FLOATS * 4;
    if (!attr_set) {
        cudaFuncSetAttribute(gemm_tf32, cudaFuncAttributeMaxDynamicSharedMemorySize, smem_bytes);
        attr_set = true;
    }
    dim3 grid(divup(Mcols, GBN), divup(Nrows, GBM));
    gemm_tf32<<<grid, 256, smem_bytes>>>(A, B, C, Nrows, Mcols);
}

static void run_gat_layer(const Scratch& s,
                          const float* h_in, const float* W,
                          const float* al, const float* ar,
                          const float* bias, const float* res,
                          int D, float* out, bool do_elu) {
    const int N = NN;
    const int F = 2 * D;

    launch_gemm(h_in, W, s.ft, N, F);
    el_er_kernel<<<divup(N * 2, 256), 256>>>(s.ft, al, ar, s.el, s.er, N, 2, D);
    node_softmax<<<divup(N * 32, 256), 256>>>(s.rowptr, s.esrc, s.el, s.er, s.w, N);
    int bdim = divup(F, 32) * 32;
    node_aggregate<<<N, bdim>>>(s.rowptr, s.esrc, s.ft, s.w, bias, res, out, F, D, do_elu ? 1 : 0);
}

extern "C" void kernel_launch(void* const* d_in, const int* in_sizes, int n_in,
                              void* d_out, int out_size) {
    const float* x      = (const float*)d_in[0];
    const int*   src    = (const int*)d_in[1];
    const int*   dst    = (const int*)d_in[2];
    const float* W0     = (const float*)d_in[3];
    const float* al0    = (const float*)d_in[4];
    const float* ar0    = (const float*)d_in[5];
    const float* b0     = (const float*)d_in[6];
    const float* W1     = (const float*)d_in[7];
    const float* al1    = (const float*)d_in[8];
    const float* ar1    = (const float*)d_in[9];
    const float* b1     = (const float*)d_in[10];
    const float* W2     = (const float*)d_in[11];
    const float* al2    = (const float*)d_in[12];
    const float* ar2    = (const float*)d_in[13];
    const float* b2     = (const float*)d_in[14];
    const float* res_W2 = (const float*)d_in[15];
    float* out = (float*)d_out;

    Scratch s;
    get_scratch(s);

    const int N = NN, E = EE;

    // ---- CSR build (shared by all 3 layers) ----
    zero_deg<<<divup(N, 256), 256>>>(s.deg, N);
    hist_dst<<<divup(E, 256), 256>>>(dst, s.deg, E);
    exscan_kernel<<<1, 1024>>>(s.deg, s.rowptr, s.cursor, N);
    fill_csr<<<divup(E, 256), 256>>>(src, dst, s.cursor, s.esrc, E);

    // ---- layer 0: no residual, ELU, D=64 ----
    run_gat_layer(s, x, W0, al0, ar0, b0, nullptr, 64, s.h, true);

    // ---- layer 1: identity residual, ELU, D=64 ----
    run_gat_layer(s, s.h, W1, al1, ar1, b1, s.h, 64, s.h, true);

    // ---- layer 2: linear residual h@res_W2, no activation, D=97 ----
    launch_gemm(s.h, res_W2, s.res2, N, 194);
    run_gat_layer(s, s.h, W2, al2, ar2, b2, s.res2, 97, s.rst, false);

    // ---- mean over heads + drop last node ----
    final_kernel<<<divup((N - 1) * 97, 256), 256>>>(s.rst, out, N - 1, 97);
}